// round 13
// baseline (speedup 1.0000x reference)
#include <cuda_runtime.h>
#include <cstddef>

#define BB   2
#define LL   512
#define HH   128
#define NH   8
#define HD   16

// ---------------- scratch (static device globals; no allocs) ----------------
__device__ float g_q  [BB*LL*HH];            // Q projection        [b,l,128]
__device__ float g_ka [BB*LL*HH];            // K + abs_pos_k       [b,l,128]
__device__ float g_va [BB*LL*HH];            // V + abs_pos_v       [b,l,128]

// ---------------- kernel 1: QKV projections as tiled GEMM -------------------
__global__ void __launch_bounds__(256) k_proj(
    const float* __restrict__ x,  const float* __restrict__ apk,
    const float* __restrict__ apv,
    const float* __restrict__ Wq, const float* __restrict__ bq,
    const float* __restrict__ Wk, const float* __restrict__ bk,
    const float* __restrict__ Wv, const float* __restrict__ bv)
{
    __shared__ float Xs[32][68];   // [kc][token]
    __shared__ float Ws[32][36];   // [kc][out]

    int t  = threadIdx.x;
    int m0 = blockIdx.x * 64;      // token tile base
    int n0 = blockIdx.y * 32;      // output tile base
    int z  = blockIdx.z;           // matrix select

    const float* W;  const float* bias; const float* add; float* dst;
    if (z == 0)      { W = Wq; bias = bq; add = nullptr; dst = g_q;  }
    else if (z == 1) { W = Wk; bias = bk; add = apk;     dst = g_ka; }
    else             { W = Wv; bias = bv; add = apv;     dst = g_va; }

    int tm = t >> 3;               // 0..31 -> 2 tokens each
    int tn = t & 7;                // 0..7  -> 4 outputs each

    float4 acc0 = make_float4(0.f,0.f,0.f,0.f);
    float4 acc1 = make_float4(0.f,0.f,0.f,0.f);

    for (int k0 = 0; k0 < HH; k0 += 32) {
        {
            int idx = t;
#pragma unroll
            for (int rep = 0; rep < 2; rep++, idx += 256) {
                int m = idx >> 3, k4 = idx & 7;
                float4 v = *reinterpret_cast<const float4*>(
                    &x[(size_t)(m0 + m)*HH + k0 + k4*4]);
                Xs[k4*4+0][m] = v.x; Xs[k4*4+1][m] = v.y;
                Xs[k4*4+2][m] = v.z; Xs[k4*4+3][m] = v.w;
            }
        }
        {
            int kc = t >> 3, n4 = t & 7;
            float4 v = *reinterpret_cast<const float4*>(
                &W[(size_t)(k0 + kc)*HH + n0 + n4*4]);
            *reinterpret_cast<float4*>(&Ws[kc][n4*4]) = v;
        }
        __syncthreads();
#pragma unroll
        for (int kc = 0; kc < 32; kc++) {
            float4 w = *reinterpret_cast<const float4*>(&Ws[kc][tn*4]);
            float x0 = Xs[kc][tm*2 + 0];
            float x1 = Xs[kc][tm*2 + 1];
            acc0.x = fmaf(x0, w.x, acc0.x); acc0.y = fmaf(x0, w.y, acc0.y);
            acc0.z = fmaf(x0, w.z, acc0.z); acc0.w = fmaf(x0, w.w, acc0.w);
            acc1.x = fmaf(x1, w.x, acc1.x); acc1.y = fmaf(x1, w.y, acc1.y);
            acc1.z = fmaf(x1, w.z, acc1.z); acc1.w = fmaf(x1, w.w, acc1.w);
        }
        __syncthreads();
    }

    float4 bz = *reinterpret_cast<const float4*>(&bias[n0 + tn*4]);
    acc0.x += bz.x; acc0.y += bz.y; acc0.z += bz.z; acc0.w += bz.w;
    acc1.x += bz.x; acc1.y += bz.y; acc1.z += bz.z; acc1.w += bz.w;

    size_t o0 = (size_t)(m0 + tm*2 + 0)*HH + n0 + tn*4;
    size_t o1 = (size_t)(m0 + tm*2 + 1)*HH + n0 + tn*4;
    if (add) {
        float4 a0 = *reinterpret_cast<const float4*>(&add[o0]);
        float4 a1 = *reinterpret_cast<const float4*>(&add[o1]);
        acc0.x += a0.x; acc0.y += a0.y; acc0.z += a0.z; acc0.w += a0.w;
        acc1.x += a1.x; acc1.y += a1.y; acc1.z += a1.z; acc1.w += a1.w;
    }
    *reinterpret_cast<float4*>(&dst[o0]) = acc0;
    *reinterpret_cast<float4*>(&dst[o1]) = acc1;
}

// ---------------- kernel 2: single-pass online-softmax, 2 queries/block -----
// ka/va (and Wo) rows are read ONCE and serve BOTH queries -> L2 traffic for
// those streams halves (the R12 profile showed LTS, not DRAM, was the cap).
// Two independent online-softmax chains share the c/d row registers.
__global__ void __launch_bounds__(256, 3) k_fused(
    const float* __restrict__ time_k,
    const float* __restrict__ time_v,
    const float* __restrict__ mask,
    const float* __restrict__ Wo,
    const float* __restrict__ bo,
    float* __restrict__ out)
{
    int bq0 = blockIdx.x * 2;            // first of 2 consecutive queries
    int b   = bq0 >> 9, q0 = bq0 & 511;  // q1 = q0+1 (same batch: 512 even)
    __shared__ __align__(16) float qs2[2][HH];   // q rows, later ctx rows
    __shared__ float ms2[2][LL];                 // mask rows, later reducers
    __shared__ float4 accbuf[2][8*32];           // per-query per-warp ctx
    __shared__ float mbuf[2][8*NH], sbuf[2][8*NH];

    int t = threadIdx.x, w = t >> 5, l = t & 31;

    if (t < 2*HH) qs2[t >> 7][t & 127] = g_q[(size_t)(bq0 + (t >> 7))*HH + (t & 127)];
    for (int i = t; i < 2*LL; i += 256)
        ms2[i >> 9][i & 511] = mask[((size_t)b*LL + q0 + (i >> 9))*LL + (i & 511)];
    __syncthreads();

    int h  = l >> 2;
    int k0 = w * 64;
    float4 qv0 = reinterpret_cast<const float4*>(qs2[0])[l];
    float4 qv1 = reinterpret_cast<const float4*>(qs2[1])[l];

    const float4* kab  = reinterpret_cast<const float4*>(g_ka + (size_t)b*(LL*HH)) + l;
    const float4* vab  = reinterpret_cast<const float4*>(g_va + (size_t)b*(LL*HH)) + l;
    const float4* tk0b = reinterpret_cast<const float4*>(time_k + (size_t)(bq0  )*(LL*HH)) + l;
    const float4* tk1b = reinterpret_cast<const float4*>(time_k + (size_t)(bq0+1)*(LL*HH)) + l;
    const float4* tv0b = reinterpret_cast<const float4*>(time_v + (size_t)(bq0  )*(LL*HH)) + l;
    const float4* tv1b = reinterpret_cast<const float4*>(time_v + (size_t)(bq0+1)*(LL*HH)) + l;

    float  m0r = -1e30f, s0r = 0.f, m1r = -1e30f, s1r = 0.f;
    float4 acc0 = make_float4(0.f,0.f,0.f,0.f);
    float4 acc1 = make_float4(0.f,0.f,0.f,0.f);

    for (int k = k0; k < k0 + 64; k += 2) {
        // 12 outstanding LDG.128 per lane; c/d shared by both queries
        float4 c0  = kab [(size_t)(k+0)*32];
        float4 c1  = kab [(size_t)(k+1)*32];
        float4 d0  = vab [(size_t)(k+0)*32];
        float4 d1  = vab [(size_t)(k+1)*32];
        float4 a00 = tk0b[(size_t)(k+0)*32];
        float4 a01 = tk0b[(size_t)(k+1)*32];
        float4 a10 = tk1b[(size_t)(k+0)*32];
        float4 a11 = tk1b[(size_t)(k+1)*32];
        float4 b00 = tv0b[(size_t)(k+0)*32];
        float4 b01 = tv0b[(size_t)(k+1)*32];
        float4 b10 = tv1b[(size_t)(k+0)*32];
        float4 b11 = tv1b[(size_t)(k+1)*32];

        float p00 = (a00.x+c0.x)*qv0.x + (a00.y+c0.y)*qv0.y
                  + (a00.z+c0.z)*qv0.z + (a00.w+c0.w)*qv0.w;
        float p01 = (a01.x+c1.x)*qv0.x + (a01.y+c1.y)*qv0.y
                  + (a01.z+c1.z)*qv0.z + (a01.w+c1.w)*qv0.w;
        float p10 = (a10.x+c0.x)*qv1.x + (a10.y+c0.y)*qv1.y
                  + (a10.z+c0.z)*qv1.z + (a10.w+c0.w)*qv1.w;
        float p11 = (a11.x+c1.x)*qv1.x + (a11.y+c1.y)*qv1.y
                  + (a11.z+c1.z)*qv1.z + (a11.w+c1.w)*qv1.w;
        p00 += __shfl_xor_sync(0xffffffffu, p00, 1);
        p00 += __shfl_xor_sync(0xffffffffu, p00, 2);
        p01 += __shfl_xor_sync(0xffffffffu, p01, 1);
        p01 += __shfl_xor_sync(0xffffffffu, p01, 2);
        p10 += __shfl_xor_sync(0xffffffffu, p10, 1);
        p10 += __shfl_xor_sync(0xffffffffu, p10, 2);
        p11 += __shfl_xor_sync(0xffffffffu, p11, 1);
        p11 += __shfl_xor_sync(0xffffffffu, p11, 2);

        // value rows (shared adds computed once)
        float vx0 = b00.x+d0.x, vy0 = b00.y+d0.y, vz0 = b00.z+d0.z, vw0 = b00.w+d0.w;
        float vx1 = b01.x+d1.x, vy1 = b01.y+d1.y, vz1 = b01.z+d1.z, vw1 = b01.w+d1.w;
        float ux0 = b10.x+d0.x, uy0 = b10.y+d0.y, uz0 = b10.z+d0.z, uw0 = b10.w+d0.w;
        float ux1 = b11.x+d1.x, uy1 = b11.y+d1.y, uz1 = b11.z+d1.z, uw1 = b11.w+d1.w;

        {   // query 0 online update
            float s0 = fmaf(p00, 0.25f, ms2[0][k  ]);
            float s1 = fmaf(p01, 0.25f, ms2[0][k+1]);
            float mn = fmaxf(m0r, fmaxf(s0, s1));
            float sc = __expf(m0r - mn);
            float e0 = __expf(s0 - mn);
            float e1 = __expf(s1 - mn);
            s0r = fmaf(s0r, sc, e0 + e1);
            acc0.x = fmaf(acc0.x, sc, fmaf(e0, vx0, e1*vx1));
            acc0.y = fmaf(acc0.y, sc, fmaf(e0, vy0, e1*vy1));
            acc0.z = fmaf(acc0.z, sc, fmaf(e0, vz0, e1*vz1));
            acc0.w = fmaf(acc0.w, sc, fmaf(e0, vw0, e1*vw1));
            m0r = mn;
        }
        {   // query 1 online update (independent chain)
            float s0 = fmaf(p10, 0.25f, ms2[1][k  ]);
            float s1 = fmaf(p11, 0.25f, ms2[1][k+1]);
            float mn = fmaxf(m1r, fmaxf(s0, s1));
            float sc = __expf(m1r - mn);
            float e0 = __expf(s0 - mn);
            float e1 = __expf(s1 - mn);
            s1r = fmaf(s1r, sc, e0 + e1);
            acc1.x = fmaf(acc1.x, sc, fmaf(e0, ux0, e1*ux1));
            acc1.y = fmaf(acc1.y, sc, fmaf(e0, uy0, e1*uy1));
            acc1.z = fmaf(acc1.z, sc, fmaf(e0, uz0, e1*uz1));
            acc1.w = fmaf(acc1.w, sc, fmaf(e0, uw0, e1*uw1));
            m1r = mn;
        }
    }

    accbuf[0][w*32 + l] = acc0;
    accbuf[1][w*32 + l] = acc1;
    if ((l & 3) == 0) {
        mbuf[0][w*NH + h] = m0r;  sbuf[0][w*NH + h] = s0r;
        mbuf[1][w*NH + h] = m1r;  sbuf[1][w*NH + h] = s1r;
    }
    __syncthreads();

    // ---- cross-warp softmax merge: t<64, qq = t>>5, lane = t&31 ----
    if (t < 64) {
        int qq = t >> 5, ln = t & 31, hh = ln >> 2;
        float M = -1e30f;
#pragma unroll
        for (int ww = 0; ww < 8; ww++) M = fmaxf(M, mbuf[qq][ww*NH + hh]);
        float4 tot = make_float4(0.f, 0.f, 0.f, 0.f);
        float  st  = 0.f;
#pragma unroll
        for (int ww = 0; ww < 8; ww++) {
            float f = __expf(mbuf[qq][ww*NH + hh] - M);
            float4 u = accbuf[qq][ww*32 + ln];
            tot.x = fmaf(f, u.x, tot.x);
            tot.y = fmaf(f, u.y, tot.y);
            tot.z = fmaf(f, u.z, tot.z);
            tot.w = fmaf(f, u.w, tot.w);
            st = fmaf(f, sbuf[qq][ww*NH + hh], st);
        }
        float inv = 1.f / st;
        tot.x *= inv; tot.y *= inv; tot.z *= inv; tot.w *= inv;
        reinterpret_cast<float4*>(qs2[qq])[ln] = tot;   // ctx rows into smem
    }
    __syncthreads();

    // ---- epilogue: both queries' out = ctx @ Wo + bo, Wo read once ----
    {
        int j = t & 127, half = t >> 7;
        const float* Wrow = Wo + (size_t)(half*64)*HH + j;
        float a0 = 0.f, a1 = 0.f;
#pragma unroll 8
        for (int i = 0; i < 64; i++) {
            float wv = Wrow[(size_t)i*HH];
            a0 = fmaf(qs2[0][half*64 + i], wv, a0);
            a1 = fmaf(qs2[1][half*64 + i], wv, a1);
        }
        ms2[0][half*128 + j] = a0;
        ms2[1][half*128 + j] = a1;
    }
    __syncthreads();
    if (t < HH) {
        out[(size_t)(bq0  )*HH + t] = ms2[0][t] + ms2[0][128 + t] + bo[t];
        out[(size_t)(bq0+1)*HH + t] = ms2[1][t] + ms2[1][128 + t] + bo[t];
    }
}

// ---------------- launch ----------------------------------------------------
extern "C" void kernel_launch(void* const* d_in, const int* in_sizes, int n_in,
                              void* d_out, int out_size)
{
    const float* x      = (const float*)d_in[0];
    const float* time_k = (const float*)d_in[1];
    const float* time_v = (const float*)d_in[2];
    const float* apk    = (const float*)d_in[3];
    const float* apv    = (const float*)d_in[4];
    const float* mask   = (const float*)d_in[5];
    const float* Wq     = (const float*)d_in[6];
    const float* bq     = (const float*)d_in[7];
    const float* Wk     = (const float*)d_in[8];
    const float* bk     = (const float*)d_in[9];
    const float* Wv     = (const float*)d_in[10];
    const float* bv     = (const float*)d_in[11];
    const float* Wo     = (const float*)d_in[12];
    const float* bo     = (const float*)d_in[13];

    {
        dim3 g(16, 4, 3);     // 16 token tiles x 4 output tiles x 3 matrices
        k_proj<<<g, 256>>>(x, apk, apv, Wq, bq, Wk, bk, Wv, bv);
    }
    k_fused<<<BB*LL/2, 256>>>(time_k, time_v, mask, Wo, bo, (float*)d_out);
}